// round 17
// baseline (speedup 1.0000x reference)
#include <cuda_runtime.h>

#define NB 32
#define NA 5
#define NC 80
#define NH 76
#define NW 76
#define HW (NH*NW)            // 5776
#define MAXT 50
#define CHS (NA*(5+NC))       // 425
#define NBLK (NB*MAXT)        // 1600
#define BT 128
#define GPP (HW/4)            // 1444 float4 groups per plane
#define GPB (GPP*NA)          // 7220 groups per batch
#define GPC 145               // groups per chunk = ceil(7220/50)
#define GPR (NW/4)            // 19 groups per row

__constant__ float c_aw[5] = {1.3221f, 3.19275f, 5.05587f, 9.47112f, 11.2364f};
__constant__ float c_ah[5] = {1.73145f, 4.00944f, 8.09892f, 4.84053f, 10.0071f};

// static scratch — no allocation, no atomics on data path.
__device__ unsigned g_count = 0;        // finished-block counter
__device__ float    g_part[NBLK];       // per-block partial sums

__device__ __forceinline__ float sigm(float v) {
    return __fdividef(1.f, 1.f + __expf(-v));
}

// ================================================================ main
// Cell-centric: each block streams 1/50 of its batch's cells exactly once
// (coalesced float4), tests each cell against the batch's 50 targets via
// per-row bitmasks, and applies noobj exclusion as a per-cell OR (no atomics).
__global__ __launch_bounds__(BT, 11) void k_main(const float* __restrict__ out,
                                                 const float* __restrict__ tgt,
                                                 float* __restrict__ res) {
    int blk = blockIdx.x;
    int b = blk / MAXT, t = blk - b*MAXT;
    int tid = threadIdx.x;

    float accA = 0.f;       // sum of non-excluded conf^2 (x0.5 at end)
    float contribM = 0.f;   // matched terms (already scaled)

    // ---- per-batch target table in shared ----
    __shared__ float4 s_ta[MAXT];    // gx0 gx1 gy0 gy1  (gt box edges)
    __shared__ float4 s_tb2[MAXT];   // gw gh 0.375*gw*gh pad
    __shared__ int4   s_box[MAXT];   // xlo xhi ylo yhi  (exact 0.4 window, cell idx)
    __shared__ int    s_cell[MAXT];  // cell-in-batch of target
    __shared__ int    s_wcell[MAXT]; // winner ? cell : -1
    __shared__ unsigned long long s_jm[NH];   // targets whose y-window covers row j
    __shared__ unsigned long long s_wjm[NH];  // winners whose matched row == j
    __shared__ unsigned s_msk[2];
    __shared__ float    s_par[8];    // own target: gx gy gw gh | (int) bn gi gj cls

    // build1: per-target geometry
    if (tid < 64) {
        bool okf = false;
        if (tid < MAXT) {
            const float* tp = tgt + (b*MAXT + tid)*5;
            okf = (tp[1] != 0.f);
            float gx = tp[1]*NW, gy = tp[2]*NH, gw = tp[3]*NW, gh = tp[4]*NH;
            float best = -1.f; int bn = 0;
            #pragma unroll
            for (int a = 0; a < NA; a++) {
                float aw = c_aw[a], ah = c_ah[a];
                float inter = fminf(gw, aw) * fminf(gh, ah);
                float iou   = __fdividef(inter, gw*gh + aw*ah - inter);
                if (iou > best) { best = iou; bn = a; }
            }
            int gi = max(0, min(NW-1, (int)gx));
            int gj = max(0, min(NH-1, (int)gy));
            s_cell[tid] = (bn*NH + gj)*NW + gi;
            s_ta[tid]  = make_float4(gx - 0.5f*gw, gx + 0.5f*gw, gy - 0.5f*gh, gy + 0.5f*gh);
            s_tb2[tid] = make_float4(gw, gh, 0.375f*gw*gh, 0.f);
            int xlo = max(0,    (int)floorf(gx - 0.4f*gw - 1e-3f));
            int xhi = min(NW-1, (int)floorf(gx + 0.4f*gw + 1e-3f));
            int ylo = max(0,    (int)floorf(gy - 0.4f*gh - 1e-3f));
            int yhi = min(NH-1, (int)floorf(gy + 0.4f*gh + 1e-3f));
            s_box[tid] = make_int4(xlo, xhi, ylo, yhi);
            if (tid == t) {
                s_par[0] = gx; s_par[1] = gy; s_par[2] = gw; s_par[3] = gh;
                ((int*)s_par)[4] = bn; ((int*)s_par)[5] = gi; ((int*)s_par)[6] = gj;
                ((int*)s_par)[7] = (int)tp[0];
            }
        }
        unsigned bal = __ballot_sync(0xFFFFFFFFu, okf);
        if ((tid & 31) == 0) s_msk[tid >> 5] = bal;
    }
    __syncthreads();

    unsigned long long okm = (unsigned long long)s_msk[0]
                           | ((unsigned long long)s_msk[1] << 32);
    unsigned long long inv = ~okm;
    int V = inv ? (__ffsll((long long)inv) - 1) : 64;     // valid targets = [0, V), V <= 50

    // build2: winners (last-write-wins dedup)
    if (tid < MAXT) {
        int w = (tid < V) ? 1 : 0;
        if (w) for (int u = tid+1; u < V; u++)
            if (s_cell[u] == s_cell[tid]) { w = 0; break; }
        s_wcell[tid] = w ? s_cell[tid] : -1;
    }
    __syncthreads();

    // build3: per-row masks
    if (tid < NH) {
        unsigned long long m = 0, wm = 0;
        for (int u = 0; u < V; u++) {
            int4 bx = s_box[u];
            if (bx.z <= tid && tid <= bx.w) m |= 1ull << u;
            int wc = s_wcell[u];
            if (wc >= 0 && ((wc / NW) % NH) == tid) wm |= 1ull << u;
        }
        s_jm[tid] = m; s_wjm[tid] = wm;
    }
    __syncthreads();

    int winner = (t < MAXT) && (s_wcell[t] >= 0);
    int bn = ((const int*)s_par)[4];
    int gi = ((const int*)s_par)[5];
    int gj = ((const int*)s_par)[6];
    int obase = (b*CHS + bn*(5+NC))*HW + gj*NW + gi;

    // ---- phase B: matched-cell loss (winner blocks; 3 warps, 80-wide log-softmax) ----
    if (winner) {
        __shared__ float sm[3], ss[3];
        int lane = tid & 31, wid = tid >> 5;
        const float* lg = out + obase + 5*HW;
        if (tid < 96) {
            unsigned mask = 0xFFFFFFFFu;
            float v = (tid < NC) ? __ldg(lg + tid*HW) : -1e30f;
            float m = v;
            #pragma unroll
            for (int off = 16; off > 0; off >>= 1) m = fmaxf(m, __shfl_xor_sync(mask, m, off));
            if (lane == 0) sm[wid] = m;
        }
        __syncthreads();
        if (tid < 96) {
            unsigned mask = 0xFFFFFFFFu;
            float mx = fmaxf(sm[0], fmaxf(sm[1], sm[2]));
            float v = (tid < NC) ? __ldg(lg + tid*HW) : -1e30f;
            float e = (tid < NC) ? __expf(v - mx) : 0.f;
            #pragma unroll
            for (int off = 16; off > 0; off >>= 1) e += __shfl_xor_sync(mask, e, off);
            if (lane == 0) ss[wid] = e;
        }
        __syncthreads();
        if (tid == 0) {
            float gx = s_par[0], gy = s_par[1], gw = s_par[2], gh = s_par[3];
            float mxv = fmaxf(sm[0], fmaxf(sm[1], sm[2]));
            float s   = ss[0] + ss[1] + ss[2];
            int   tc  = ((const int*)s_par)[7];
            float ce  = mxv + __logf(s) - __ldg(lg + tc*HW);

            float o0 = out[obase],      o1 = out[obase+HW];
            float o2 = out[obase+2*HW], o3 = out[obase+3*HW];
            float conf = sigm(out[obase+4*HW]);
            float mpx = sigm(o0) + (float)gi;
            float mpy = sigm(o1) + (float)gj;
            float mpw = __expf(o2) * c_aw[bn];
            float mph = __expf(o3) * c_ah[bn];
            float lx = fminf(gx - 0.5f*gw, mpx - 0.5f*mpw);
            float Rx = fmaxf(gx + 0.5f*gw, mpx + 0.5f*mpw);
            float ly = fminf(gy - 0.5f*gh, mpy - 0.5f*mph);
            float Ry = fmaxf(gy + 0.5f*gh, mpy + 0.5f*mph);
            float cw = gw + mpw - (Rx - lx);
            float ch = gh + mph - (Ry - ly);
            float inter = (cw <= 0.f || ch <= 0.f) ? 0.f : cw*ch;
            float t_iou = __fdividef(inter, gw*gh + mpw*mph - inter);

            float dx = sigm(o0) - (gx - (float)gi);
            float dy = sigm(o1) - (gy - (float)gj);
            float dw = o2 - __logf(__fdividef(gw, c_aw[bn]));
            float dh = o3 - __logf(__fdividef(gh, c_ah[bn]));
            float dc = conf - t_iou;
            contribM = 0.5f*(dx*dx + dy*dy + dw*dw + dh*dh) + 2.5f*dc*dc + ce;
            // NOTE: no conf^2 subtraction here — exclusion handled in the cell pass via s_wjm.
        }
    }

    // ---- main pass: stream this chunk's cells once; exclusion = OR over targets ----
    {
        const float* bbase = out + (size_t)b*CHS*HW;
        int g0 = t*GPC;
        int g1 = min(GPB, g0 + GPC);
        for (int g = g0 + tid; g < g1; g += BT) {
            int a  = g / GPP;
            int r  = g - a*GPP;
            int j  = r / GPR;
            int ib = (r - j*GPR) << 2;
            const float* pb = bbase + (size_t)a*(5+NC)*HW + (j*NW + ib);
            float4 c4 = __ldg((const float4*)(pb + 4*HW));
            float s0 = sigm(c4.x), s1 = sigm(c4.y), s2 = sigm(c4.z), s3 = sigm(c4.w);

            int exb = 0;
            int cib0 = (a*NH + j)*NW + ib;
            // matched-cell exclusion
            unsigned long long wm = s_wjm[j];
            while (wm) {
                int u = __ffsll((long long)wm) - 1; wm &= wm - 1;
                int d = s_wcell[u] - cib0;            // encodes anchor too
                if (d >= 0 && d < 4) exb |= 1 << d;
            }
            // spatial window hits
            unsigned long long hm = 0;
            unsigned long long m = s_jm[j];
            while (m) {
                int u = __ffsll((long long)m) - 1; m &= m - 1;
                int4 bx = s_box[u];
                if (ib <= bx.y && ib + 3 >= bx.x) hm |= 1ull << u;
            }
            if (hm) {
                float4 v0 = __ldg((const float4*)pb);
                float4 v1 = __ldg((const float4*)(pb + HW));
                float4 v2 = __ldg((const float4*)(pb + 2*HW));
                float4 v3 = __ldg((const float4*)(pb + 3*HW));
                float aw = c_aw[a], ah = c_ah[a];
                float px0 = sigm(v0.x) + (float)(ib+0), px1 = sigm(v0.y) + (float)(ib+1);
                float px2 = sigm(v0.z) + (float)(ib+2), px3 = sigm(v0.w) + (float)(ib+3);
                float fj = (float)j;
                float py0 = sigm(v1.x) + fj, py1 = sigm(v1.y) + fj;
                float py2 = sigm(v1.z) + fj, py3 = sigm(v1.w) + fj;
                float pw0 = __expf(v2.x)*aw, pw1 = __expf(v2.y)*aw;
                float pw2 = __expf(v2.z)*aw, pw3 = __expf(v2.w)*aw;
                float ph0 = __expf(v3.x)*ah, ph1 = __expf(v3.y)*ah;
                float ph2 = __expf(v3.z)*ah, ph3 = __expf(v3.w)*ah;
                while (hm) {
                    int u = __ffsll((long long)hm) - 1; hm &= hm - 1;
                    float4 ta = s_ta[u];
                    float4 tb = s_tb2[u];
                    int4   bx = s_box[u];
                    #define CELLTEST(c, PX, PY, PW, PH)                                      \
                        if (!((exb >> c) & 1) && (ib+c) >= bx.x && (ib+c) <= bx.y) {         \
                            float cw = PW + tb.x - (fmaxf(PX + 0.5f*PW, ta.y)                \
                                                  - fminf(PX - 0.5f*PW, ta.x));             \
                            float ch = PH + tb.y - (fmaxf(PY + 0.5f*PH, ta.w)                \
                                                  - fminf(PY - 0.5f*PH, ta.z));             \
                            if (cw > 0.f && ch > 0.f && cw*ch > 0.375f*PW*PH + tb.z)         \
                                exb |= 1 << c;                                               \
                        }
                    CELLTEST(0, px0, py0, pw0, ph0)
                    CELLTEST(1, px1, py1, pw1, ph1)
                    CELLTEST(2, px2, py2, pw2, ph2)
                    CELLTEST(3, px3, py3, pw3, ph3)
                    #undef CELLTEST
                }
            }
            accA += ((exb & 1) ? 0.f : s0*s0) + ((exb & 2) ? 0.f : s1*s1)
                  + ((exb & 4) ? 0.f : s2*s2) + ((exb & 8) ? 0.f : s3*s3);
        }
    }

    // ---- block reduction (4 warps) -> partial store; last block reduces ----
    float v = 0.5f*accA + contribM;
    unsigned mask = 0xFFFFFFFFu;
    #pragma unroll
    for (int off = 16; off > 0; off >>= 1) v += __shfl_down_sync(mask, v, off);
    __shared__ float sw[4];
    __shared__ int   s_last;
    int lane = tid & 31, wid = tid >> 5;
    if (lane == 0) sw[wid] = v;
    __syncthreads();
    if (tid < 32) {
        v = (lane < 4) ? sw[lane] : 0.f;
        #pragma unroll
        for (int off = 2; off > 0; off >>= 1) v += __shfl_down_sync(mask, v, off);
        if (lane == 0) {
            g_part[blk] = v;
            __threadfence();
            unsigned done = atomicAdd(&g_count, 1u);
            s_last = (done == NBLK - 1);
        }
    }
    __syncthreads();
    if (s_last) {
        double d = 0.0;
        for (int k = tid; k < NBLK; k += BT) d += (double)g_part[k];
        #pragma unroll
        for (int off = 16; off > 0; off >>= 1) d += __shfl_down_sync(mask, d, off);
        __shared__ double sd[4];
        if (lane == 0) sd[wid] = d;
        __syncthreads();
        if (tid < 32) {
            d = (lane < 4) ? sd[lane] : 0.0;
            #pragma unroll
            for (int off = 2; off > 0; off >>= 1) d += __shfl_down_sync(mask, d, off);
            if (lane == 0) {
                res[0] = (float)d;
                g_count = 0;
            }
        }
    }
}

// ================================================================ launch
extern "C" void kernel_launch(void* const* d_in, const int* in_sizes, int n_in,
                              void* d_out, int out_size) {
    const float* out = (const float*)d_in[0];   // (32, 425, 76, 76)
    const float* tgt = (const float*)d_in[1];   // (32, 250)
    float* res = (float*)d_out;

    k_main<<<NBLK, BT>>>(out, tgt, res);
}